// round 8
// baseline (speedup 1.0000x reference)
#include <cuda_runtime.h>
#include <stdint.h>

// B = 1048576, D = 3, L = 16, C = 2, H = 16, S = 1.0
//   res(l) = 16 << l, side = res+1; dense l=0,1,2; hashed l>=3 (hm = 2^19)
//   offsets: 0, 4920, 40864, 315496, then +524288/level (all even)
//   table = concat(ext[524288,2], own[.,2])
//
// R8 = R2 verbatim (best: 293us; pair-merged divergent gathers, 32 regs,
// occ 86%) with ALL table gathers switched to __ldcg (L2-only, no L1
// allocate). Rationale: gathers stream 53MB through a 228KB L1 -> ~0% hit
// rate, so every L1 fill (128B into the data banks per miss) is wasted
// l1tex bank bandwidth. __ldcg skips the fill. Uniform across lanes: no new
// divergence, no new registers.

#define HASH_SPLIT 524288u
#define P2 2654435761u
#define P3 805459861u

__device__ __forceinline__ const float2* tptr(unsigned g,
                                              const float2* __restrict__ ext,
                                              const float2* __restrict__ own)
{
    return (g < HASH_SPLIT) ? (ext + g) : (own + (g - HASH_SPLIT));
}

__global__ void __launch_bounds__(256)
grid_encode_kernel(const float* __restrict__ pts,
                   const float2* __restrict__ ext,
                   const float2* __restrict__ own,
                   float2* __restrict__ out)
{
    const unsigned gtid = blockIdx.x * 256u + threadIdx.x;
    const unsigned b = gtid >> 4;
    const unsigned l = gtid & 15u;

    const float px_in = __ldg(&pts[3u * b + 0u]);
    const float py_in = __ldg(&pts[3u * b + 1u]);
    const float pz_in = __ldg(&pts[3u * b + 2u]);

    const unsigned res  = 16u << l;
    const float scale   = (float)(res - 1u);
    const unsigned side = res + 1u;

    const float posx = (px_in + 1.0f) * 0.5f * scale + 0.5f;
    const float posy = (py_in + 1.0f) * 0.5f * scale + 0.5f;
    const float posz = (pz_in + 1.0f) * 0.5f * scale + 0.5f;

    const float flx = floorf(posx);
    const float fly = floorf(posy);
    const float flz = floorf(posz);
    const float fx = posx - flx;
    const float fy = posy - fly;
    const float fz = posz - flz;
    const unsigned x0 = (unsigned)flx;
    const unsigned y0 = (unsigned)fly;
    const unsigned z0 = (unsigned)flz;

    const bool hashed = (l >= 3u);
    const unsigned off = hashed ? (315496u + (l - 3u) * 524288u)
                                : (l == 0u ? 0u : (l == 1u ? 4920u : 40864u));

    // Hash per-axis terms (uint32 wraparound; PRIMES = {1, P2, P3})
    const unsigned hy0 = y0 * P2;
    const unsigned hz0 = z0 * P3;
    const unsigned hys[2] = { hy0, hy0 + P2 };
    const unsigned hzs[2] = { hz0, hz0 + P3 };

    // Dense per-axis terms (no modulo: side^3 <= hm for l<=2)
    const unsigned side2 = side * side;
    const unsigned dys[2] = { y0 * side,  y0 * side + side };
    const unsigned dzs[2] = { z0 * side2, z0 * side2 + side2 };

    // Global indices for the 4 (y,z) pairs.
    unsigned ia[4], ib[4];
#pragma unroll
    for (int p = 0; p < 4; ++p) {
        const int cy = p & 1, cz = (p >> 1) & 1;
        unsigned a, bx;
        if (hashed) {
            const unsigned hb = hys[cy] ^ hzs[cz];
            a  = (x0 ^ hb) & (HASH_SPLIT - 1u);
            bx = ((x0 + 1u) ^ hb) & (HASH_SPLIT - 1u);
        } else {
            const unsigned db = dys[cy] + dzs[cz];
            a  = x0 + db;
            bx = a + 1u;
        }
        ia[p] = off + a;
        ib[p] = off + bx;
    }

    // Fetch: one LDG.128.cg when the pair occupies one aligned 16B slot,
    // else two LDG.64.cg. Pairs never cross level/half boundaries (all even).
    float2 v0[4], v1[4];
#pragma unroll
    for (int p = 0; p < 4; ++p) {
        const unsigned a = ia[p], bb = ib[p];
        if ((a ^ bb) == 1u) {
            const unsigned lo = a & ~1u;
            const float4 w4 = __ldcg((const float4*)tptr(lo, ext, own));
            const bool swap = (a & 1u);
            v0[p] = swap ? make_float2(w4.z, w4.w) : make_float2(w4.x, w4.y);
            v1[p] = swap ? make_float2(w4.x, w4.y) : make_float2(w4.z, w4.w);
        } else {
            v0[p] = __ldcg(tptr(a,  ext, own));
            v1[p] = __ldcg(tptr(bb, ext, own));
        }
    }

    // Trilinear weights.
    const float wx0 = 1.0f - fx, wx1 = fx;
    const float wy[2] = { 1.0f - fy, fy };
    const float wz[2] = { 1.0f - fz, fz };

    float accx = 0.0f, accy = 0.0f;
#pragma unroll
    for (int p = 0; p < 4; ++p) {
        const int cy = p & 1, cz = (p >> 1) & 1;
        const float w = wy[cy] * wz[cz];
        accx += w * (wx0 * v0[p].x + wx1 * v1[p].x);
        accy += w * (wx0 * v0[p].y + wx1 * v1[p].y);
    }

    out[gtid] = make_float2(accx, accy);
}

extern "C" void kernel_launch(void* const* d_in, const int* in_sizes, int n_in,
                              void* d_out, int out_size)
{
    const float*  pts = (const float*)d_in[0];        // [B, 3]
    const float2* ext = (const float2*)d_in[1];       // [524288, 2]
    const float2* own = (const float2*)d_in[2];       // [N_TABLE - 524288, 2]
    float2* out = (float2*)d_out;                     // [B*16] float2

    grid_encode_kernel<<<65536, 256>>>(pts, ext, own, out);
}

// round 9
// speedup vs baseline: 1.0705x; 1.0705x over previous
#include <cuda_runtime.h>
#include <stdint.h>

// B = 1048576, D = 3, L = 16, C = 2, H = 16, S = 1.0
//   res(l) = 16 << l, side = res+1; dense l=0,1,2; hashed l>=3 (hm = 2^19)
//   offsets: 0, 4920, 40864, 315496, then +524288/level (all even)
//   table = concat(ext[524288,2], own[.,2])
//
// R9 = R2 skeleton + loads-only cache split.
//   Evidence: R8 (all .cg) showed L1 filters ~12% of L2 sectors in R2 -- the
//   dense-level tables (l<=2, all inside ext[0..315496)) are L1-resident.
//   R6 (full-body split) showed the split idea pays only if the divergent
//   region is tiny. Here ONLY the 8 load instructions diverge:
//     hashed lanes: __ldcg  (L2-only: no L1 fill, no eviction of dense lines)
//     dense  lanes: __ldg, direct ext+idx (no ext/own select needed)
//   Index computation and trilinear accumulation are shared (no duplication).

#define HASH_SPLIT 524288u
#define P2 2654435761u
#define P3 805459861u

__device__ __forceinline__ const float2* tptr(unsigned g,
                                              const float2* __restrict__ ext,
                                              const float2* __restrict__ own)
{
    return (g < HASH_SPLIT) ? (ext + g) : (own + (g - HASH_SPLIT));
}

__global__ void __launch_bounds__(256)
grid_encode_kernel(const float* __restrict__ pts,
                   const float2* __restrict__ ext,
                   const float2* __restrict__ own,
                   float2* __restrict__ out)
{
    const unsigned gtid = blockIdx.x * 256u + threadIdx.x;
    const unsigned b = gtid >> 4;
    const unsigned l = gtid & 15u;

    const float px_in = __ldg(&pts[3u * b + 0u]);
    const float py_in = __ldg(&pts[3u * b + 1u]);
    const float pz_in = __ldg(&pts[3u * b + 2u]);

    const unsigned res  = 16u << l;
    const float scale   = (float)(res - 1u);
    const unsigned side = res + 1u;

    const float posx = (px_in + 1.0f) * 0.5f * scale + 0.5f;
    const float posy = (py_in + 1.0f) * 0.5f * scale + 0.5f;
    const float posz = (pz_in + 1.0f) * 0.5f * scale + 0.5f;

    const float flx = floorf(posx);
    const float fly = floorf(posy);
    const float flz = floorf(posz);
    const float fx = posx - flx;
    const float fy = posy - fly;
    const float fz = posz - flz;
    const unsigned x0 = (unsigned)flx;
    const unsigned y0 = (unsigned)fly;
    const unsigned z0 = (unsigned)flz;

    const bool hashed = (l >= 3u);
    const unsigned off = hashed ? (315496u + (l - 3u) * 524288u)
                                : (l == 0u ? 0u : (l == 1u ? 4920u : 40864u));

    // Hash per-axis terms (uint32 wraparound; PRIMES = {1, P2, P3})
    const unsigned hy0 = y0 * P2;
    const unsigned hz0 = z0 * P3;
    const unsigned hys[2] = { hy0, hy0 + P2 };
    const unsigned hzs[2] = { hz0, hz0 + P3 };

    // Dense per-axis terms (no modulo: side^3 <= hm for l<=2)
    const unsigned side2 = side * side;
    const unsigned dys[2] = { y0 * side,  y0 * side + side };
    const unsigned dzs[2] = { z0 * side2, z0 * side2 + side2 };

    // Global indices for the 4 (y,z) pairs (shared by both load arms).
    unsigned ia[4], ib[4];
#pragma unroll
    for (int p = 0; p < 4; ++p) {
        const int cy = p & 1, cz = (p >> 1) & 1;
        unsigned a, bx;
        if (hashed) {
            const unsigned hb = hys[cy] ^ hzs[cz];
            a  = (x0 ^ hb) & (HASH_SPLIT - 1u);
            bx = ((x0 + 1u) ^ hb) & (HASH_SPLIT - 1u);
        } else {
            const unsigned db = dys[cy] + dzs[cz];
            a  = x0 + db;
            bx = a + 1u;
        }
        ia[p] = off + a;
        ib[p] = off + bx;
    }

    // ---- Loads only: divergent cache-op split ----
    float2 v0[4], v1[4];
    if (hashed) {
        // L2-only gathers: no L1 allocation.
#pragma unroll
        for (int p = 0; p < 4; ++p) {
            const unsigned a = ia[p], bb = ib[p];
            if ((a ^ bb) == 1u) {
                const unsigned lo = a & ~1u;
                const float4 w4 = __ldcg((const float4*)tptr(lo, ext, own));
                const bool swap = (a & 1u);
                v0[p] = swap ? make_float2(w4.z, w4.w) : make_float2(w4.x, w4.y);
                v1[p] = swap ? make_float2(w4.x, w4.y) : make_float2(w4.z, w4.w);
            } else {
                v0[p] = __ldcg(tptr(a,  ext, own));
                v1[p] = __ldcg(tptr(bb, ext, own));
            }
        }
    } else {
        // Dense levels: all indices < 315496+... < HASH_SPLIT -> always ext.
        // Dense pairs are consecutive (b = a+1): pairable iff a even.
#pragma unroll
        for (int p = 0; p < 4; ++p) {
            const unsigned a = ia[p];
            if ((a & 1u) == 0u) {
                const float4 w4 = __ldg((const float4*)(ext + a));
                v0[p] = make_float2(w4.x, w4.y);
                v1[p] = make_float2(w4.z, w4.w);
            } else {
                v0[p] = __ldg(ext + a);
                v1[p] = __ldg(ext + a + 1u);
            }
        }
    }

    // Trilinear accumulate (shared).
    const float wx0 = 1.0f - fx, wx1 = fx;
    const float wy[2] = { 1.0f - fy, fy };
    const float wz[2] = { 1.0f - fz, fz };

    float accx = 0.0f, accy = 0.0f;
#pragma unroll
    for (int p = 0; p < 4; ++p) {
        const int cy = p & 1, cz = (p >> 1) & 1;
        const float w = wy[cy] * wz[cz];
        accx += w * (wx0 * v0[p].x + wx1 * v1[p].x);
        accy += w * (wx0 * v0[p].y + wx1 * v1[p].y);
    }

    out[gtid] = make_float2(accx, accy);
}

extern "C" void kernel_launch(void* const* d_in, const int* in_sizes, int n_in,
                              void* d_out, int out_size)
{
    const float*  pts = (const float*)d_in[0];        // [B, 3]
    const float2* ext = (const float2*)d_in[1];       // [524288, 2]
    const float2* own = (const float2*)d_in[2];       // [N_TABLE - 524288, 2]
    float2* out = (float2*)d_out;                     // [B*16] float2

    grid_encode_kernel<<<65536, 256>>>(pts, ext, own, out);
}

// round 10
// speedup vs baseline: 1.2072x; 1.1277x over previous
#include <cuda_runtime.h>
#include <stdint.h>

// B = 1048576, D = 3, L = 16, C = 2, H = 16, S = 1.0
//   res(l) = 16 << l, side = res+1; dense l=0,1,2; hashed l>=3 (hm = 2^19)
//   offsets: 0, 4920, 40864, 315496, then +524288/level (all even)
//   table = concat(ext[524288,2], own[.,2])
//
// R10 = R9 structure with .cg removed (measured: .cg costs MORE l1tex work
// on sm_103a, both in R8 and R9). Loads-only divergent split kept (worth
// ~-12us by R2/R8/R9 decomposition):
//   dense arm (l<=2): direct ext indexing, no selects, LDG.128 when even.
//   hashed arm (l>=3): pair-merged loads; ext/own select reduced to one
//     compare vs per-thread threshold T (only l==3 truly straddles the
//     ext/own boundary; l>=4 is always own, dense always ext).

#define HASH_SPLIT 524288u
#define P2 2654435761u
#define P3 805459861u

__global__ void __launch_bounds__(256)
grid_encode_kernel(const float* __restrict__ pts,
                   const float2* __restrict__ ext,
                   const float2* __restrict__ own,
                   float2* __restrict__ out)
{
    const unsigned gtid = blockIdx.x * 256u + threadIdx.x;
    const unsigned b = gtid >> 4;
    const unsigned l = gtid & 15u;

    const float px_in = __ldg(&pts[3u * b + 0u]);
    const float py_in = __ldg(&pts[3u * b + 1u]);
    const float pz_in = __ldg(&pts[3u * b + 2u]);

    const unsigned res  = 16u << l;
    const float scale   = (float)(res - 1u);
    const unsigned side = res + 1u;

    const float posx = (px_in + 1.0f) * 0.5f * scale + 0.5f;
    const float posy = (py_in + 1.0f) * 0.5f * scale + 0.5f;
    const float posz = (pz_in + 1.0f) * 0.5f * scale + 0.5f;

    const float flx = floorf(posx);
    const float fly = floorf(posy);
    const float flz = floorf(posz);
    const float fx = posx - flx;
    const float fy = posy - fly;
    const float fz = posz - flz;
    const unsigned x0 = (unsigned)flx;
    const unsigned y0 = (unsigned)fly;
    const unsigned z0 = (unsigned)flz;

    const bool hashed = (l >= 3u);
    const unsigned off = hashed ? (315496u + (l - 3u) * 524288u)
                                : (l == 0u ? 0u : (l == 1u ? 4920u : 40864u));

    // ext/own threshold: indices < T -> ext + g ; else own + (g - HASH_SPLIT).
    // l <= 2: always ext (T = max). l == 3: straddles (T = HASH_SPLIT).
    // l >= 4: always own (T = 0).
    const unsigned T = (l < 3u) ? 0xFFFFFFFFu : (l == 3u ? HASH_SPLIT : 0u);
    const float2* __restrict__ ownm = own - HASH_SPLIT;   // own base rebased

    // Hash per-axis terms (uint32 wraparound; PRIMES = {1, P2, P3})
    const unsigned hy0 = y0 * P2;
    const unsigned hz0 = z0 * P3;
    const unsigned hys[2] = { hy0, hy0 + P2 };
    const unsigned hzs[2] = { hz0, hz0 + P3 };

    // Dense per-axis terms (no modulo: side^3 <= hm for l<=2)
    const unsigned side2 = side * side;
    const unsigned dys[2] = { y0 * side,  y0 * side + side };
    const unsigned dzs[2] = { z0 * side2, z0 * side2 + side2 };

    // Global indices for the 4 (y,z) pairs (shared by both load arms).
    unsigned ia[4], ib[4];
#pragma unroll
    for (int p = 0; p < 4; ++p) {
        const int cy = p & 1, cz = (p >> 1) & 1;
        unsigned a, bx;
        if (hashed) {
            const unsigned hb = hys[cy] ^ hzs[cz];
            a  = (x0 ^ hb) & (HASH_SPLIT - 1u);
            bx = ((x0 + 1u) ^ hb) & (HASH_SPLIT - 1u);
        } else {
            const unsigned db = dys[cy] + dzs[cz];
            a  = x0 + db;
            bx = a + 1u;
        }
        ia[p] = off + a;
        ib[p] = off + bx;
    }

    // ---- Loads only: divergent arm split (both arms __ldg) ----
    float2 v0[4], v1[4];
    if (hashed) {
#pragma unroll
        for (int p = 0; p < 4; ++p) {
            const unsigned a = ia[p], bb = ib[p];
            if ((a ^ bb) == 1u) {
                // Pair shares one aligned 16B slot: single LDG.128.
                const unsigned lo = a & ~1u;
                const float2* q = (lo < T) ? (ext + lo) : (ownm + lo);
                const float4 w4 = __ldg((const float4*)q);
                const bool swap = (a & 1u);
                v0[p] = swap ? make_float2(w4.z, w4.w) : make_float2(w4.x, w4.y);
                v1[p] = swap ? make_float2(w4.x, w4.y) : make_float2(w4.z, w4.w);
            } else {
                const float2* qa = (a  < T) ? (ext + a)  : (ownm + a);
                const float2* qb = (bb < T) ? (ext + bb) : (ownm + bb);
                v0[p] = __ldg(qa);
                v1[p] = __ldg(qb);
            }
        }
    } else {
        // Dense levels: all indices inside ext; pairs consecutive (b = a+1),
        // one LDG.128 when a is even.
#pragma unroll
        for (int p = 0; p < 4; ++p) {
            const unsigned a = ia[p];
            if ((a & 1u) == 0u) {
                const float4 w4 = __ldg((const float4*)(ext + a));
                v0[p] = make_float2(w4.x, w4.y);
                v1[p] = make_float2(w4.z, w4.w);
            } else {
                v0[p] = __ldg(ext + a);
                v1[p] = __ldg(ext + a + 1u);
            }
        }
    }

    // Trilinear accumulate (shared).
    const float wx0 = 1.0f - fx, wx1 = fx;
    const float wy[2] = { 1.0f - fy, fy };
    const float wz[2] = { 1.0f - fz, fz };

    float accx = 0.0f, accy = 0.0f;
#pragma unroll
    for (int p = 0; p < 4; ++p) {
        const int cy = p & 1, cz = (p >> 1) & 1;
        const float w = wy[cy] * wz[cz];
        accx += w * (wx0 * v0[p].x + wx1 * v1[p].x);
        accy += w * (wx0 * v0[p].y + wx1 * v1[p].y);
    }

    out[gtid] = make_float2(accx, accy);
}

extern "C" void kernel_launch(void* const* d_in, const int* in_sizes, int n_in,
                              void* d_out, int out_size)
{
    const float*  pts = (const float*)d_in[0];        // [B, 3]
    const float2* ext = (const float2*)d_in[1];       // [524288, 2]
    const float2* own = (const float2*)d_in[2];       // [N_TABLE - 524288, 2]
    float2* out = (float2*)d_out;                     // [B*16] float2

    grid_encode_kernel<<<65536, 256>>>(pts, ext, own, out);
}